// round 6
// baseline (speedup 1.0000x reference)
#include <cuda_runtime.h>
#include <math.h>

#define BB 8
#define NNODE 512
#define TT 64
#define NINP 64
#define NE 128
#define NH 128
#define RTOT 4096
#define G4 512
#define WTOT 704        /* 128 (u) + 512 (gates, interleaved) + 64 (out) */

// ---------------- scratch (allocation-free: __device__ globals) ----------------
__device__ float g_An[BB*NNODE*NNODE];     // normalized adjacency
__device__ float g_dinv[RTOT];
__device__ float g_c[RTOT*NH];
__device__ float g_h[RTOT*NH];
__device__ float g_u[RTOT*NE];             // u = h @ Wpe
__device__ float g_hw[RTOT*G4];            // h @ Wgates (interleaved cols)
__device__ float g_Hu4[4*RTOT*NH];         // split-K partials of An @ u
__device__ float g_es[RTOT*NE];
__device__ float g_esW[RTOT*G4];           // es@Wtop + cvec (interleaved)
__device__ float g_Xi[RTOT*NINP];
__device__ float g_Wc[NE*WTOT];            // [Wpe | gates-interleaved | Wout]
__device__ float g_Wg[NE*G4];              // bottom gate halves (interleaved)
__device__ float g_Wtop[NE*G4];            // top gate halves (interleaved)
__device__ float g_cvec[G4];               // b + bh + bpe@Wbot (interleaved)

__device__ __forceinline__ float sigm(float x) { return 1.f / (1.f + __expf(-x)); }

// ---------------- prep kernels ----------------
__global__ void prep_weights(
    const float* __restrict__ Wpe, const float* __restrict__ bpe,
    const float* __restrict__ Wii, const float* __restrict__ bii,
    const float* __restrict__ Whi, const float* __restrict__ bhi,
    const float* __restrict__ Wif, const float* __restrict__ bif_,
    const float* __restrict__ Whf, const float* __restrict__ bhf,
    const float* __restrict__ Wig, const float* __restrict__ big_,
    const float* __restrict__ Whg, const float* __restrict__ bhg,
    const float* __restrict__ Wio, const float* __restrict__ bio,
    const float* __restrict__ Who, const float* __restrict__ bho,
    const float* __restrict__ Wout)
{
    int idx = blockIdx.x * blockDim.x + threadIdx.x;
    const float* Wg[4]  = {Wii, Wif, Wig, Wio};
    const float* Whx[4] = {Whi, Whf, Whg, Who};
    const float* bg[4]  = {bii, bif_, big_, bio};
    const float* bhx[4] = {bhi, bhf, bhg, bho};

    if (idx < NE*WTOT) {                      // Wc = [Wpe | h-gates interleaved | Wout]
        int k = idx / WTOT, j = idx % WTOT;
        float v;
        if (j < NE) v = Wpe[k*NE + j];
        else if (j < 640) { int jj = j - NE; int jh = jj >> 2, g = jj & 3; v = Whx[g][k*NH + jh]; }
        else v = Wout[k*NINP + (j - 640)];
        g_Wc[idx] = v;
    }
    int i2 = idx - NE*WTOT;
    if (i2 >= 0 && i2 < NE*G4) {              // interleaved Wg (bottom) + Wtop (top)
        int k = i2 / G4, jj = i2 % G4; int jh = jj >> 2, g = jj & 3;
        g_Wg[i2]   = Wg[g][(NE + k)*NH + jh];
        g_Wtop[i2] = Wg[g][k*NH + jh];
    }
    int i3 = i2 - NE*G4;
    if (i3 >= 0 && i3 < G4) {                 // cvec = b + bh + bpe@Wbot (interleaved)
        int jh = i3 >> 2, g = i3 & 3;
        float s = bg[g][jh] + bhx[g][jh];
        for (int k = 0; k < NE; k++) s += bpe[k] * Wg[g][(NE + k)*NH + jh];
        g_cvec[i3] = s;
    }
}

__global__ void prep_dinv(const float* __restrict__ A)
{
    int row = blockIdx.x;
    const float* Ar = A + (size_t)row * NNODE;
    float s = 0.f;
    for (int j = threadIdx.x; j < NNODE; j += blockDim.x) s += Ar[j];
    __shared__ float red[4];
    for (int o = 16; o > 0; o >>= 1) s += __shfl_down_sync(0xffffffff, s, o);
    if ((threadIdx.x & 31) == 0) red[threadIdx.x >> 5] = s;
    __syncthreads();
    if (threadIdx.x == 0) {
        float d = red[0] + red[1] + red[2] + red[3];
        g_dinv[row] = d > 0.f ? rsqrtf(d) : 0.f;
    }
}

__global__ void prep_An(const float* __restrict__ A)
{
    int idx = blockIdx.x * blockDim.x + threadIdx.x;
    if (idx >= BB*NNODE*NNODE) return;
    int j  = idx & (NNODE - 1);
    int bi = idx >> 9;
    int b  = idx >> 18;
    g_An[idx] = A[idx] * g_dinv[bi] * g_dinv[(b << 9) + j];
}

__global__ void prep_init(const float* __restrict__ X, float* __restrict__ out)
{
    int idx = blockIdx.x * blockDim.x + threadIdx.x;
    if (idx < RTOT*G4) { g_hw[idx] = 0.f; g_Hu4[idx] = 0.f; }
    if (idx < RTOT*NH) { g_h[idx] = 0.f; g_c[idx] = 0.f; }
    if (idx < RTOT*NINP) {
        int r = idx >> 6, c = idx & 63;
        float v = X[(size_t)r * (TT*NINP) + c];
        g_Xi[idx] = v;
        out[(size_t)r * (TT*NINP) + c] = v;     // t = 0 slice
    }
}

__global__ void prep_es(const float* __restrict__ X,
                        const float* __restrict__ Wse, const float* __restrict__ bse)
{
    int r = blockIdx.x;
    __shared__ float xs[NINP];
    if (threadIdx.x < NINP) xs[threadIdx.x] = X[(size_t)r * (TT*NINP) + threadIdx.x];
    __syncthreads();
    int j = threadIdx.x;
    float s = bse[j];
    #pragma unroll 8
    for (int k = 0; k < NINP; k++) s += xs[k] * Wse[k*NE + j];
    g_es[r*NE + j] = s;
}

// ------------- one-time SGEMM: esW = es @ Wtop + cvec -------------
#define KC 16
__global__ __launch_bounds__(256) void sgemm_t32(
    const float* __restrict__ A, int lda,
    const float* __restrict__ B, int ldb,
    float* __restrict__ C, int ldc,
    int K, const float* __restrict__ bias)
{
    const float* Ab = A + (size_t)blockIdx.x * 32 * lda;
    const float* Bb = B + (size_t)blockIdx.y * 128;
    float*       Cb = C + (size_t)blockIdx.x * 32 * ldc + (size_t)blockIdx.y * 128;

    __shared__ float AsT[KC][36];
    __shared__ float Bss[KC][128];

    int tid = threadIdx.x;
    int tx = tid & 31, ty = tid >> 5;
    int r0 = ty * 4, c0 = tx * 4;

    float acc[4][4];
    #pragma unroll
    for (int i = 0; i < 4; i++)
        #pragma unroll
        for (int j = 0; j < 4; j++) acc[i][j] = 0.f;

    for (int kk = 0; kk < K; kk += KC) {
        #pragma unroll
        for (int e = 0; e < 2; e++) {
            int el = 2*tid + e;
            int ar = el >> 4, ak = el & 15;
            AsT[ak][ar] = Ab[(size_t)ar * lda + kk + ak];
        }
        #pragma unroll
        for (int e = 0; e < 8; e++) {
            int el = tid + e * 256;
            int bk = el >> 7, bc = el & 127;
            Bss[bk][bc] = Bb[(size_t)(kk + bk) * ldb + bc];
        }
        __syncthreads();
        #pragma unroll
        for (int k = 0; k < KC; k++) {
            float4 av = *(const float4*)&AsT[k][r0];
            float4 bv = *(const float4*)&Bss[k][c0];
            float a[4] = {av.x, av.y, av.z, av.w};
            float b[4] = {bv.x, bv.y, bv.z, bv.w};
            #pragma unroll
            for (int i = 0; i < 4; i++)
                #pragma unroll
                for (int j = 0; j < 4; j++) acc[i][j] += a[i] * b[j];
        }
        __syncthreads();
    }
    #pragma unroll
    for (int i = 0; i < 4; i++) {
        float4 v = make_float4(acc[i][0], acc[i][1], acc[i][2], acc[i][3]);
        if (bias) {
            const float4 bv = *(const float4*)&bias[blockIdx.y*128 + c0];
            v.x += bv.x; v.y += bv.y; v.z += bv.z; v.w += bv.w;
        }
        *(float4*)&Cb[(size_t)(r0 + i) * ldc + c0] = v;
    }
}

// ------------- K1: [u | hw | out_{t-1}] = h @ Wc  (M=4096, K=128, N=704) -------------
// tile 128x64, 128 threads, 8x8 micro. grid (32, ncolTiles)
__global__ __launch_bounds__(128) void k1(
    float* __restrict__ out, const float* __restrict__ bout, int t, int colbase)
{
    __shared__ float AsT[32][132];
    __shared__ float Bs[32][68];

    const int tid = threadIdx.x;
    const int ty = tid >> 3, tx = tid & 7;      // 16 row-groups x 8 col-groups
    const int rowg = blockIdx.x * 128;
    const int colg = colbase + blockIdx.y * 64;

    float acc[8][8];
    #pragma unroll
    for (int i = 0; i < 8; i++)
        #pragma unroll
        for (int j = 0; j < 8; j++) acc[i][j] = 0.f;

    for (int kk = 0; kk < NE; kk += 32) {
        #pragma unroll
        for (int k4 = 0; k4 < 8; k4++) {        // A: 128 rows x 32 k of h (transposed)
            float4 v = *(const float4*)&g_h[(size_t)(rowg + tid)*NH + kk + k4*4];
            AsT[k4*4+0][tid] = v.x; AsT[k4*4+1][tid] = v.y;
            AsT[k4*4+2][tid] = v.z; AsT[k4*4+3][tid] = v.w;
        }
        {                                        // B: 32 x 64 of Wc
            int bk = tid >> 2, c0 = (tid & 3) * 16;
            #pragma unroll
            for (int j = 0; j < 4; j++)
                *(float4*)&Bs[bk][c0 + j*4] =
                    *(const float4*)&g_Wc[(size_t)(kk + bk)*WTOT + colg + c0 + j*4];
        }
        __syncthreads();
        #pragma unroll
        for (int k = 0; k < 32; k++) {
            float a[8], b[8];
            *(float4*)&a[0] = *(const float4*)&AsT[k][ty*8];
            *(float4*)&a[4] = *(const float4*)&AsT[k][ty*8 + 4];
            *(float4*)&b[0] = *(const float4*)&Bs[k][tx*8];
            *(float4*)&b[4] = *(const float4*)&Bs[k][tx*8 + 4];
            #pragma unroll
            for (int i = 0; i < 8; i++)
                #pragma unroll
                for (int j = 0; j < 8; j++) acc[i][j] += a[i] * b[j];
        }
        __syncthreads();
    }

    if (colg < NE) {                             // -> g_u
        #pragma unroll
        for (int i = 0; i < 8; i++) {
            size_t row = rowg + ty*8 + i;
            *(float4*)&g_u[row*NE + colg + tx*8] =
                make_float4(acc[i][0], acc[i][1], acc[i][2], acc[i][3]);
            *(float4*)&g_u[row*NE + colg + tx*8 + 4] =
                make_float4(acc[i][4], acc[i][5], acc[i][6], acc[i][7]);
        }
    } else if (colg < 640) {                     // -> g_hw (interleaved gate cols)
        #pragma unroll
        for (int i = 0; i < 8; i++) {
            size_t row = rowg + ty*8 + i;
            int c = colg - NE + tx*8;
            *(float4*)&g_hw[row*G4 + c] =
                make_float4(acc[i][0], acc[i][1], acc[i][2], acc[i][3]);
            *(float4*)&g_hw[row*G4 + c + 4] =
                make_float4(acc[i][4], acc[i][5], acc[i][6], acc[i][7]);
        }
    } else {                                     // -> out_{t-1} = Xi + h@Wout + bout
        int o = colg - 640 + tx*8;
        float4 b0 = *(const float4*)&bout[o];
        float4 b1 = *(const float4*)&bout[o + 4];
        #pragma unroll
        for (int i = 0; i < 8; i++) {
            size_t row = rowg + ty*8 + i;
            float4 x0 = *(const float4*)&g_Xi[row*NINP + o];
            float4 x1 = *(const float4*)&g_Xi[row*NINP + o + 4];
            float4 v0 = make_float4(acc[i][0]+x0.x+b0.x, acc[i][1]+x0.y+b0.y,
                                    acc[i][2]+x0.z+b0.z, acc[i][3]+x0.w+b0.w);
            float4 v1 = make_float4(acc[i][4]+x1.x+b1.x, acc[i][5]+x1.y+b1.y,
                                    acc[i][6]+x1.z+b1.z, acc[i][7]+x1.w+b1.w);
            *(float4*)&g_Xi[row*NINP + o]     = v0;
            *(float4*)&g_Xi[row*NINP + o + 4] = v1;
            *(float4*)&out[row*(TT*NINP) + (size_t)(t-1)*NINP + o]     = v0;
            *(float4*)&out[row*(TT*NINP) + (size_t)(t-1)*NINP + o + 4] = v1;
        }
    }
}

// ------------- K2: Hu partial (split-K x4): An @ u -------------
// tile 64x128 per (batch, ksplit), 128 threads, 8x8 micro. grid (8, 1, 32)
__global__ __launch_bounds__(128) void k2()
{
    __shared__ float AsT[32][68];
    __shared__ float Bs[32][132];

    const int tid = threadIdx.x;
    const int ty = tid >> 4, tx = tid & 15;     // 8 x 16
    const int b  = blockIdx.z >> 2, ks = blockIdx.z & 3;
    const int rowg = blockIdx.x * 64;
    const int kbase = ks * 128;
    const size_t anb = (size_t)b * NNODE * NNODE;

    float acc[8][8];
    #pragma unroll
    for (int i = 0; i < 8; i++)
        #pragma unroll
        for (int j = 0; j < 8; j++) acc[i][j] = 0.f;

    for (int kk = 0; kk < 128; kk += 32) {
        {                                        // A: 64 rows x 32 k of An (transposed)
            int r = tid >> 1, kh = (tid & 1) * 16;
            #pragma unroll
            for (int j = 0; j < 4; j++) {
                float4 v = *(const float4*)&g_An[anb + (size_t)(rowg + r)*NNODE + kbase + kk + kh + j*4];
                AsT[kh + j*4 + 0][r] = v.x; AsT[kh + j*4 + 1][r] = v.y;
                AsT[kh + j*4 + 2][r] = v.z; AsT[kh + j*4 + 3][r] = v.w;
            }
        }
        {                                        // B: 32 k x 128 of u
            int bk = tid >> 2, c0 = (tid & 3) * 32;
            #pragma unroll
            for (int j = 0; j < 8; j++)
                *(float4*)&Bs[bk][c0 + j*4] =
                    *(const float4*)&g_u[(size_t)(b*NNODE + kbase + kk + bk)*NE + c0 + j*4];
        }
        __syncthreads();
        #pragma unroll
        for (int k = 0; k < 32; k++) {
            float a[8], bvv[8];
            *(float4*)&a[0] = *(const float4*)&AsT[k][ty*8];
            *(float4*)&a[4] = *(const float4*)&AsT[k][ty*8 + 4];
            *(float4*)&bvv[0] = *(const float4*)&Bs[k][tx*8];
            *(float4*)&bvv[4] = *(const float4*)&Bs[k][tx*8 + 4];
            #pragma unroll
            for (int i = 0; i < 8; i++)
                #pragma unroll
                for (int j = 0; j < 8; j++) acc[i][j] += a[i] * bvv[j];
        }
        __syncthreads();
    }
    #pragma unroll
    for (int i = 0; i < 8; i++) {
        size_t row = (size_t)b*NNODE + rowg + ty*8 + i;
        size_t base = (size_t)ks*(RTOT*NH) + row*NH + tx*8;
        *(float4*)&g_Hu4[base]     = make_float4(acc[i][0], acc[i][1], acc[i][2], acc[i][3]);
        *(float4*)&g_Hu4[base + 4] = make_float4(acc[i][4], acc[i][5], acc[i][6], acc[i][7]);
    }
}

// ------------- K3: gates = esW + hw + Hu@Wg ; LSTM state update -------------
// tile 32 rows x 256 gate-cols (64 hidden), 128 threads, 8x8 micro. grid (128, 2)
__global__ __launch_bounds__(128) void k3()
{
    __shared__ float AsT[128][36];               // Hu (merged), transposed [k][row]
    __shared__ float Bs[32][260];

    const int tid = threadIdx.x;
    const int ty = tid >> 5, tx = tid & 31;      // 4 x 32
    const int rg = blockIdx.x * 32;
    const int ch = blockIdx.y;                   // column half: hidden [ch*64, ch*64+64)

    {                                            // prologue: merge 4 Hu partials, transpose
        int row = tid & 31, kseg = (tid >> 5) * 32;
        #pragma unroll
        for (int k4 = 0; k4 < 8; k4++) {
            size_t idx = (size_t)(rg + row)*NH + kseg + k4*4;
            float4 s0 = *(const float4*)&g_Hu4[idx];
            float4 s1 = *(const float4*)&g_Hu4[(size_t)RTOT*NH + idx];
            float4 s2 = *(const float4*)&g_Hu4[2*(size_t)RTOT*NH + idx];
            float4 s3 = *(const float4*)&g_Hu4[3*(size_t)RTOT*NH + idx];
            AsT[kseg + k4*4 + 0][row] = s0.x + s1.x + s2.x + s3.x;
            AsT[kseg + k4*4 + 1][row] = s0.y + s1.y + s2.y + s3.y;
            AsT[kseg + k4*4 + 2][row] = s0.z + s1.z + s2.z + s3.z;
            AsT[kseg + k4*4 + 3][row] = s0.w + s1.w + s2.w + s3.w;
        }
    }
    __syncthreads();

    float acc[8][8];
    #pragma unroll
    for (int i = 0; i < 8; i++) {                // init from esW + hw
        size_t base = (size_t)(rg + ty*8 + i)*G4 + ch*256 + tx*8;
        float4 e0 = *(const float4*)&g_esW[base];
        float4 e1 = *(const float4*)&g_esW[base + 4];
        float4 w0 = *(const float4*)&g_hw[base];
        float4 w1 = *(const float4*)&g_hw[base + 4];
        acc[i][0] = e0.x + w0.x; acc[i][1] = e0.y + w0.y;
        acc[i][2] = e0.z + w0.z; acc[i][3] = e0.w + w0.w;
        acc[i][4] = e1.x + w1.x; acc[i][5] = e1.y + w1.y;
        acc[i][6] = e1.z + w1.z; acc[i][7] = e1.w + w1.w;
    }

    for (int kk = 0; kk < NE; kk += 32) {
        {                                        // B: 32 k x 256 of Wg
            int bk = tid >> 2, c0 = (tid & 3) * 64;
            #pragma unroll
            for (int j = 0; j < 16; j++)
                *(float4*)&Bs[bk][c0 + j*4] =
                    *(const float4*)&g_Wg[(size_t)(kk + bk)*G4 + ch*256 + c0 + j*4];
        }
        __syncthreads();
        #pragma unroll
        for (int k = 0; k < 32; k++) {
            float a[8], bvv[8];
            *(float4*)&a[0] = *(const float4*)&AsT[kk + k][ty*8];
            *(float4*)&a[4] = *(const float4*)&AsT[kk + k][ty*8 + 4];
            *(float4*)&bvv[0] = *(const float4*)&Bs[k][tx*8];
            *(float4*)&bvv[4] = *(const float4*)&Bs[k][tx*8 + 4];
            #pragma unroll
            for (int i = 0; i < 8; i++)
                #pragma unroll
                for (int j = 0; j < 8; j++) acc[i][j] += a[i] * bvv[j];
        }
        __syncthreads();
    }

    // elementwise LSTM: each thread has 8 rows x 2 hidden, gate quads (i,f,g,o)
    #pragma unroll
    for (int i = 0; i < 8; i++) {
        size_t row = rg + ty*8 + i;
        int hp = ch*64 + tx*2;
        float2 cold = *(const float2*)&g_c[row*NH + hp];
        float i0 = sigm(acc[i][0]), f0 = sigm(acc[i][1]);
        float gg0 = tanhf(acc[i][2]), o0 = sigm(acc[i][3]);
        float i1 = sigm(acc[i][4]), f1 = sigm(acc[i][5]);
        float gg1 = tanhf(acc[i][6]), o1 = sigm(acc[i][7]);
        float c0n = f0 * cold.x + i0 * gg0;
        float c1n = f1 * cold.y + i1 * gg1;
        *(float2*)&g_c[row*NH + hp] = make_float2(c0n, c1n);
        *(float2*)&g_h[row*NH + hp] = make_float2(o0 * tanhf(c0n), o1 * tanhf(c1n));
    }
}

// ---------------- launch ----------------
extern "C" void kernel_launch(void* const* d_in, const int* in_sizes, int n_in,
                              void* d_out, int out_size)
{
    const float* X    = (const float*)d_in[0];
    const float* A    = (const float*)d_in[1];
    const float* Wse  = (const float*)d_in[2];
    const float* bse  = (const float*)d_in[3];
    const float* Wpe  = (const float*)d_in[4];
    const float* bpe  = (const float*)d_in[5];
    const float* Wii  = (const float*)d_in[6];
    const float* bii  = (const float*)d_in[7];
    const float* Whi  = (const float*)d_in[8];
    const float* bhi  = (const float*)d_in[9];
    const float* Wif  = (const float*)d_in[10];
    const float* bif_ = (const float*)d_in[11];
    const float* Whf  = (const float*)d_in[12];
    const float* bhf  = (const float*)d_in[13];
    const float* Wig  = (const float*)d_in[14];
    const float* big_ = (const float*)d_in[15];
    const float* Whg  = (const float*)d_in[16];
    const float* bhg  = (const float*)d_in[17];
    const float* Wio  = (const float*)d_in[18];
    const float* bio  = (const float*)d_in[19];
    const float* Who  = (const float*)d_in[20];
    const float* bho  = (const float*)d_in[21];
    const float* Wout = (const float*)d_in[22];
    const float* bout = (const float*)d_in[23];
    float* out = (float*)d_out;

    float *p_es, *p_esW, *p_Wtop, *p_cvec;
    cudaGetSymbolAddress((void**)&p_es,   g_es);
    cudaGetSymbolAddress((void**)&p_esW,  g_esW);
    cudaGetSymbolAddress((void**)&p_Wtop, g_Wtop);
    cudaGetSymbolAddress((void**)&p_cvec, g_cvec);

    int wtotal = NE*WTOT + NE*G4 + G4;
    prep_weights<<<(wtotal + 255)/256, 256>>>(
        Wpe, bpe, Wii, bii, Whi, bhi, Wif, bif_, Whf, bhf,
        Wig, big_, Whg, bhg, Wio, bio, Who, bho, Wout);
    prep_dinv<<<RTOT, 128>>>(A);
    prep_An<<<(BB*NNODE*NNODE + 255)/256, 256>>>(A);
    prep_init<<<(RTOT*G4 + 255)/256, 256>>>(X, out);
    prep_es<<<RTOT, 128>>>(X, Wse, bse);

    // esW = es @ Wtop + cvec   (M=4096, K=128, N=512 interleaved)
    sgemm_t32<<<dim3(RTOT/32, G4/128), 256>>>(
        p_es, NE, p_Wtop, G4, p_esW, G4, NE, p_cvec);

    // t = 1: h0 = 0 -> u/hw/Hu are zero (pre-zeroed); only gates needed
    k3<<<dim3(RTOT/32, 2), 128>>>();

    for (int t = 2; t < TT; ++t) {
        k1<<<dim3(RTOT/128, WTOT/64), 128>>>(out, bout, t, 0);   // uv + out_{t-1}
        k2<<<dim3(NNODE/64, 1, 4*BB), 128>>>();                  // Hu partials
        k3<<<dim3(RTOT/32, 2), 128>>>();                         // gates + state
    }
    // tail: out_63 from h_63 (only the Wout column tile)
    k1<<<dim3(RTOT/128, 1), 128>>>(out, bout, TT, 640);
}